// round 10
// baseline (speedup 1.0000x reference)
#include <cuda_runtime.h>
#include <cuda_bf16.h>
#include <cstdint>

// ---------------------------------------------------------------------------
// octree_level — replicating the reference AS EXECUTED (jax x64 disabled:
// int64 keys silently wrap to int32).
//
// Wrapped key <-> (x mod 256, y, z). Therefore:
//   parent class    c = (px mod 256, py, pz),  px = x>>1
//   negative classes (cmod >= 128) -> valid=False -> (-1,-1,-1) rows at FRONT
//   positive classes (cmod < 128)  -> coord rows sorted lex (cmod,py,pz)
//   occupancy(child) = exists leaf with (x mod 256, y, z) == child
//
// Bitmaps:
//   g_childbm : bit (pmp<<3)|o, pmp = ((x&255)>>1)<<18 | (y>>1)<<9 | (z>>1)
//               -> 2^28 bits (32 MB); byte pmp IS the occupancy row
//   g_parbm   : bit pcls = ((x>>1)&255)<<18 | (y>>1)<<9 | (z>>1)
//               -> 2^26 bits (8 MB); lower half = valid classes, upper = neg
// ---------------------------------------------------------------------------

#define NCW (1u << 23)   // child bitmap words (2^28 bits = 32 MB)
#define NPW (1u << 21)   // parent bitmap words (2^26 bits = 8 MB)
#define CBLK 512         // count blocks (cover all NPW words)
#define EBLK 256         // emit blocks (lower half only)
#define TPB  256
#define WPT  16          // words per thread: CBLK*TPB*WPT = 2^21 = NPW

__device__ unsigned int g_childbm[NCW];
__device__ unsigned int g_parbm[NPW];
__device__ unsigned int g_bsum[CBLK];
__device__ unsigned int g_boff[EBLK];
__device__ unsigned int g_nneg;
__device__ unsigned int g_nend;
__device__ unsigned int g_ctr;   // blocks-done counter (reset by last block)

// ---- clear both bitmaps ----
__global__ void k_clear() {
    unsigned idx    = blockIdx.x * blockDim.x + threadIdx.x;
    unsigned stride = gridDim.x * blockDim.x;
    uint4 z = make_uint4(0u, 0u, 0u, 0u);
    uint4* c4 = reinterpret_cast<uint4*>(g_childbm);
    for (unsigned i = idx; i < NCW / 4; i += stride) c4[i] = z;
    uint4* p4 = reinterpret_cast<uint4*>(g_parbm);
    for (unsigned i = idx; i < NPW / 4; i += stride) p4[i] = z;
}

// ---- scatter leaves ----
__global__ void k_scatter(const float* __restrict__ leaf, int n) {
    int i = blockIdx.x * blockDim.x + threadIdx.x;
    if (i >= n) return;
    int x = (int)floorf(leaf[3 * i + 0]);
    int y = (int)floorf(leaf[3 * i + 1]);
    int z = (int)floorf(leaf[3 * i + 2]);
    unsigned pcls = (((unsigned)(x >> 1) & 255u) << 18)
                  | ((unsigned)(y >> 1) << 9) | (unsigned)(z >> 1);
    atomicOr(&g_parbm[pcls >> 5], 1u << (pcls & 31));
    unsigned pmp = ((((unsigned)x & 255u) >> 1) << 18)
                 | ((unsigned)(y >> 1) << 9) | (unsigned)(z >> 1);
    unsigned o = ((unsigned)(x & 1) << 2) | ((unsigned)(y & 1) << 1) | (unsigned)(z & 1);
    unsigned bit = (pmp << 3) | o;                 // < 2^28
    atomicOr(&g_childbm[bit >> 5], 1u << (bit & 31));
}

// ---- fused count + scan (last-block-does-scan, threadfence reduction) ----
__global__ void k_countscan() {
    __shared__ unsigned swarp[8];
    __shared__ bool s_last;
    int t = threadIdx.x;
    int lane = t & 31, warp = t >> 5;

    // count phase: popcount this block's 128K-bit stripe
    unsigned base = blockIdx.x * (TPB * WPT) + t * WPT;
    const uint4* w4 = reinterpret_cast<const uint4*>(g_parbm + base);
    unsigned c = 0;
#pragma unroll
    for (int v = 0; v < WPT / 4; v++) {
        uint4 a = w4[v];
        c += __popc(a.x) + __popc(a.y) + __popc(a.z) + __popc(a.w);
    }
    unsigned r = c;
#pragma unroll
    for (int off = 16; off; off >>= 1) r += __shfl_down_sync(0xffffffffu, r, off);
    if (lane == 0) swarp[warp] = r;
    __syncthreads();
    if (t == 0) {
        unsigned tot = 0;
#pragma unroll
        for (int i = 0; i < 8; i++) tot += swarp[i];
        g_bsum[blockIdx.x] = tot;
        __threadfence();
        unsigned d = atomicAdd(&g_ctr, 1u);
        s_last = (d == CBLK - 1);
    }
    __syncthreads();
    if (!s_last) return;

    // scan phase (last block only): Nneg = sum upper 256; exclusive prefix
    // over lower 256 with base Nneg.
    __threadfence();
    unsigned vlo = g_bsum[t];
    unsigned vup = g_bsum[256 + t];
    unsigned ru = vup;
#pragma unroll
    for (int off = 16; off; off >>= 1) ru += __shfl_down_sync(0xffffffffu, ru, off);
    unsigned inc = vlo;
#pragma unroll
    for (int off = 1; off < 32; off <<= 1) {
        unsigned u = __shfl_up_sync(0xffffffffu, inc, off);
        if (lane >= off) inc += u;
    }
    __shared__ unsigned s_up[8], s_lo[8], s_base[8];
    if (lane == 0)  s_up[warp] = ru;
    if (lane == 31) s_lo[warp] = inc;
    __syncthreads();
    if (t == 0) {
        unsigned nneg = 0;
#pragma unroll
        for (int i = 0; i < 8; i++) nneg += s_up[i];
        unsigned acc = nneg;
#pragma unroll
        for (int i = 0; i < 8; i++) { s_base[i] = acc; acc += s_lo[i]; }
        g_nneg = nneg;
        g_nend = acc;
        g_ctr  = 0;            // reset for next graph replay (deterministic)
    }
    __syncthreads();
    g_boff[t] = s_base[warp] + inc - vlo;   // exclusive prefix + front offset
}

// ---- fill sentinel rows: [0, Nneg) and [Nend, n) ----
__global__ void k_fill(float* __restrict__ outPC, float* __restrict__ outOcc, int n) {
    int r = blockIdx.x * blockDim.x + threadIdx.x;
    if (r >= n) return;
    if ((unsigned)r >= g_nneg && (unsigned)r < g_nend) return;
    outPC[3 * r + 0] = -1.0f;
    outPC[3 * r + 1] = -1.0f;
    outPC[3 * r + 2] = -1.0f;
    float4 z4 = make_float4(0.f, 0.f, 0.f, 0.f);
    float4* occ4 = reinterpret_cast<float4*>(outOcc + 8 * (size_t)r);
    occ4[0] = z4;
    occ4[1] = z4;
}

// ---- enumerate lower-half parent classes, emit coords + occupancy ----
__global__ void k_emit(float* __restrict__ outPC, float* __restrict__ outOcc) {
    int t = threadIdx.x;
    int lane = t & 31, warp = t >> 5;
    unsigned base = blockIdx.x * (TPB * WPT) + t * WPT;   // words in lower half
    unsigned words[WPT];
    const uint4* w4 = reinterpret_cast<const uint4*>(g_parbm + base);
    unsigned c = 0;
#pragma unroll
    for (int v = 0; v < WPT / 4; v++) {
        uint4 a = w4[v];
        words[4 * v + 0] = a.x;
        words[4 * v + 1] = a.y;
        words[4 * v + 2] = a.z;
        words[4 * v + 3] = a.w;
        c += __popc(a.x) + __popc(a.y) + __popc(a.z) + __popc(a.w);
    }
    // block exclusive scan of c via warp shuffles
    unsigned inc = c;
#pragma unroll
    for (int off = 1; off < 32; off <<= 1) {
        unsigned u = __shfl_up_sync(0xffffffffu, inc, off);
        if (lane >= off) inc += u;
    }
    __shared__ unsigned swsum[8], swbase[8];
    if (lane == 31) swsum[warp] = inc;
    __syncthreads();
    if (t == 0) {
        unsigned acc = 0;
#pragma unroll
        for (int i = 0; i < 8; i++) { swbase[i] = acc; acc += swsum[i]; }
    }
    __syncthreads();
    unsigned pos = g_boff[blockIdx.x] + swbase[warp] + (inc - c);

#pragma unroll
    for (int w = 0; w < WPT; w++) {
        unsigned word = words[w];
        unsigned wi = base + w;
        while (word) {
            int b = __ffs(word) - 1;
            word &= word - 1;
            unsigned p = wi * 32u + (unsigned)b;      // class, p < 2^25
            outPC[3 * pos + 0] = (float)(p >> 18);          // px mod 256, < 128
            outPC[3 * pos + 1] = (float)((p >> 9) & 511u);  // py
            outPC[3 * pos + 2] = (float)(p & 511u);         // pz
            unsigned mask = (__ldg(&g_childbm[p >> 2]) >> ((p & 3u) * 8u)) & 0xFFu;
            float4 lo, hi;
            lo.x = (float)( mask       & 1u);
            lo.y = (float)((mask >> 1) & 1u);
            lo.z = (float)((mask >> 2) & 1u);
            lo.w = (float)((mask >> 3) & 1u);
            hi.x = (float)((mask >> 4) & 1u);
            hi.y = (float)((mask >> 5) & 1u);
            hi.z = (float)((mask >> 6) & 1u);
            hi.w = (float)((mask >> 7) & 1u);
            float4* occ4 = reinterpret_cast<float4*>(outOcc + 8 * (size_t)pos);
            occ4[0] = lo;
            occ4[1] = hi;
            pos++;
        }
    }
}

extern "C" void kernel_launch(void* const* d_in, const int* in_sizes, int n_in,
                              void* d_out, int out_size) {
    const float* leaf = (const float*)d_in[0];
    int n = in_sizes[0] / 3;
    float* out    = (float*)d_out;
    float* outPC  = out;                      // [n,3] parent coords (wrapped semantics)
    float* outOcc = out + (size_t)n * 3;      // [n,8] occupancy

    k_clear    <<<2048, 256>>>();
    k_scatter  <<<(n + 255) / 256, 256>>>(leaf, n);
    k_countscan<<<CBLK, TPB>>>();
    k_fill     <<<(n + 255) / 256, 256>>>(outPC, outOcc, n);
    k_emit     <<<EBLK, TPB>>>(outPC, outOcc);
}

// round 12
// speedup vs baseline: 1.0531x; 1.0531x over previous
#include <cuda_runtime.h>
#include <cuda_bf16.h>
#include <cstdint>

// ---------------------------------------------------------------------------
// octree_level — replicating the reference AS EXECUTED (jax x64 disabled:
// int64 keys silently wrap to int32).
//
// Wrapped key <-> (x mod 256, y, z). Therefore:
//   parent class    c = (px mod 256, py, pz),  px = x>>1
//   negative classes (cmod >= 128) -> valid=False -> (-1,-1,-1) rows at FRONT
//   positive classes (cmod < 128)  -> coord rows sorted lex (cmod,py,pz)
//   occupancy(child) = exists leaf with (x mod 256, y, z) == child
//
// Bitmaps:
//   g_childbm : bit (pmp<<3)|o, pmp = ((x&255)>>1)<<18 | (y>>1)<<9 | (z>>1)
//               -> 2^28 bits (32 MB); byte pmp IS the occupancy row
//   g_parbm   : bit pcls = ((x>>1)&255)<<18 | (y>>1)<<9 | (z>>1)
//               -> 2^26 bits (8 MB); lower half = valid classes, upper = neg
// ---------------------------------------------------------------------------

#define NCW (1u << 23)   // child bitmap words (2^28 bits = 32 MB)
#define NPW (1u << 21)   // parent bitmap words (2^26 bits = 8 MB)
#define CBLK 512         // count blocks (cover all NPW words)
#define EBLK 256         // emit blocks (lower half only)
#define TPB  256
#define WPT  16          // words per thread: CBLK*TPB*WPT = 2^21 = NPW

__device__ unsigned int g_childbm[NCW];
__device__ unsigned int g_parbm[NPW];
__device__ unsigned int g_bsum[CBLK];
__device__ unsigned int g_boff[EBLK];
__device__ unsigned int g_nneg;
__device__ unsigned int g_nend;
__device__ unsigned int g_ctr;   // blocks-done counter (reset by last block)

// ---- clear both bitmaps ----
__global__ void k_clear() {
    unsigned idx    = blockIdx.x * blockDim.x + threadIdx.x;
    unsigned stride = gridDim.x * blockDim.x;
    uint4 z = make_uint4(0u, 0u, 0u, 0u);
    uint4* c4 = reinterpret_cast<uint4*>(g_childbm);
    for (unsigned i = idx; i < NCW / 4; i += stride) c4[i] = z;
    uint4* p4 = reinterpret_cast<uint4*>(g_parbm);
    for (unsigned i = idx; i < NPW / 4; i += stride) p4[i] = z;
}

// ---- scatter leaves ----
__global__ void k_scatter(const float* __restrict__ leaf, int n) {
    int i = blockIdx.x * blockDim.x + threadIdx.x;
    if (i >= n) return;
    int x = (int)floorf(leaf[3 * i + 0]);
    int y = (int)floorf(leaf[3 * i + 1]);
    int z = (int)floorf(leaf[3 * i + 2]);
    unsigned pcls = (((unsigned)(x >> 1) & 255u) << 18)
                  | ((unsigned)(y >> 1) << 9) | (unsigned)(z >> 1);
    atomicOr(&g_parbm[pcls >> 5], 1u << (pcls & 31));
    unsigned pmp = ((((unsigned)x & 255u) >> 1) << 18)
                 | ((unsigned)(y >> 1) << 9) | (unsigned)(z >> 1);
    unsigned o = ((unsigned)(x & 1) << 2) | ((unsigned)(y & 1) << 1) | (unsigned)(z & 1);
    unsigned bit = (pmp << 3) | o;                 // < 2^28
    atomicOr(&g_childbm[bit >> 5], 1u << (bit & 31));
}

// ---- fused count + scan (last-block-does-scan, threadfence reduction) ----
__global__ void k_countscan() {
    __shared__ unsigned swarp[8];
    __shared__ bool s_last;
    int t = threadIdx.x;
    int lane = t & 31, warp = t >> 5;

    unsigned base = blockIdx.x * (TPB * WPT) + t * WPT;
    const uint4* w4 = reinterpret_cast<const uint4*>(g_parbm + base);
    unsigned c = 0;
#pragma unroll
    for (int v = 0; v < WPT / 4; v++) {
        uint4 a = w4[v];
        c += __popc(a.x) + __popc(a.y) + __popc(a.z) + __popc(a.w);
    }
    unsigned r = c;
#pragma unroll
    for (int off = 16; off; off >>= 1) r += __shfl_down_sync(0xffffffffu, r, off);
    if (lane == 0) swarp[warp] = r;
    __syncthreads();
    if (t == 0) {
        unsigned tot = 0;
#pragma unroll
        for (int i = 0; i < 8; i++) tot += swarp[i];
        g_bsum[blockIdx.x] = tot;
        __threadfence();
        unsigned d = atomicAdd(&g_ctr, 1u);
        s_last = (d == CBLK - 1);
    }
    __syncthreads();
    if (!s_last) return;

    __threadfence();
    unsigned vlo = g_bsum[t];
    unsigned vup = g_bsum[256 + t];
    unsigned ru = vup;
#pragma unroll
    for (int off = 16; off; off >>= 1) ru += __shfl_down_sync(0xffffffffu, ru, off);
    unsigned inc = vlo;
#pragma unroll
    for (int off = 1; off < 32; off <<= 1) {
        unsigned u = __shfl_up_sync(0xffffffffu, inc, off);
        if (lane >= off) inc += u;
    }
    __shared__ unsigned s_up[8], s_lo[8], s_base[8];
    if (lane == 0)  s_up[warp] = ru;
    if (lane == 31) s_lo[warp] = inc;
    __syncthreads();
    if (t == 0) {
        unsigned nneg = 0;
#pragma unroll
        for (int i = 0; i < 8; i++) nneg += s_up[i];
        unsigned acc = nneg;
#pragma unroll
        for (int i = 0; i < 8; i++) { s_base[i] = acc; acc += s_lo[i]; }
        g_nneg = nneg;
        g_nend = acc;
        g_ctr  = 0;            // reset for next graph replay (deterministic)
    }
    __syncthreads();
    g_boff[t] = s_base[warp] + inc - vlo;   // exclusive prefix + front offset
}

// ---- fill sentinel RANGES with vector stores (contiguous, not per-row) ----
// PC : floats [0, 3*Nneg) = -1   and [3*Nend, 3n) = -1
// Occ: floats [0, 8*Nneg) =  0   and [8*Nend, 8n) =  0  (16B-aligned ranges)
__global__ void k_fill(float* __restrict__ outPC, float* __restrict__ outOcc, int n) {
    unsigned nneg = g_nneg, nend = g_nend;
    unsigned idx    = blockIdx.x * blockDim.x + threadIdx.x;
    unsigned stride = gridDim.x * blockDim.x;
    const float4 m4 = make_float4(-1.f, -1.f, -1.f, -1.f);
    const float4 z4 = make_float4(0.f, 0.f, 0.f, 0.f);

    // PC front [0, 3*nneg)
    {
        unsigned e = 3u * nneg;
        float4* p = reinterpret_cast<float4*>(outPC);
        for (unsigned i = idx; i < (e >> 2); i += stride) p[i] = m4;
        if (idx < (e & 3u)) outPC[(e & ~3u) + idx] = -1.0f;
    }
    // PC tail [3*nend, 3n)
    {
        unsigned s = 3u * nend, e = 3u * (unsigned)n;   // e divisible by 4 (n=2M)
        unsigned sa = (s + 3u) & ~3u;                   // aligned start
        if (idx < (sa - s) && s + idx < e) outPC[s + idx] = -1.0f;
        if (sa < e) {
            float4* p = reinterpret_cast<float4*>(outPC + sa);
            unsigned m = (e - sa) >> 2;
            for (unsigned i = idx; i < m; i += stride) p[i] = m4;
        }
    }
    // Occ front [0, 8*nneg): 2*nneg float4s
    {
        float4* p = reinterpret_cast<float4*>(outOcc);
        unsigned m = 2u * nneg;
        for (unsigned i = idx; i < m; i += stride) p[i] = z4;
    }
    // Occ tail [8*nend, 8n): 2*(n-nend) float4s
    {
        float4* p = reinterpret_cast<float4*>(outOcc + 8u * (size_t)nend);
        unsigned m = 2u * ((unsigned)n - nend);
        for (unsigned i = idx; i < m; i += stride) p[i] = z4;
    }
}

// ---- enumerate lower-half parent classes, emit coords + occupancy ----
__global__ void k_emit(float* __restrict__ outPC, float* __restrict__ outOcc) {
    int t = threadIdx.x;
    int lane = t & 31, warp = t >> 5;
    unsigned base = blockIdx.x * (TPB * WPT) + t * WPT;   // words in lower half
    unsigned words[WPT];
    const uint4* w4 = reinterpret_cast<const uint4*>(g_parbm + base);
    unsigned c = 0;
#pragma unroll
    for (int v = 0; v < WPT / 4; v++) {
        uint4 a = w4[v];
        words[4 * v + 0] = a.x;
        words[4 * v + 1] = a.y;
        words[4 * v + 2] = a.z;
        words[4 * v + 3] = a.w;
        c += __popc(a.x) + __popc(a.y) + __popc(a.z) + __popc(a.w);
    }
    unsigned inc = c;
#pragma unroll
    for (int off = 1; off < 32; off <<= 1) {
        unsigned u = __shfl_up_sync(0xffffffffu, inc, off);
        if (lane >= off) inc += u;
    }
    __shared__ unsigned swsum[8], swbase[8];
    if (lane == 31) swsum[warp] = inc;
    __syncthreads();
    if (t == 0) {
        unsigned acc = 0;
#pragma unroll
        for (int i = 0; i < 8; i++) { swbase[i] = acc; acc += swsum[i]; }
    }
    __syncthreads();
    unsigned pos = g_boff[blockIdx.x] + swbase[warp] + (inc - c);

#pragma unroll
    for (int w = 0; w < WPT; w++) {
        unsigned word = words[w];
        unsigned wi = base + w;
        while (word) {
            int b = __ffs(word) - 1;
            word &= word - 1;
            unsigned p = wi * 32u + (unsigned)b;      // class, p < 2^25
            outPC[3 * pos + 0] = (float)(p >> 18);          // px mod 256, < 128
            outPC[3 * pos + 1] = (float)((p >> 9) & 511u);  // py
            outPC[3 * pos + 2] = (float)(p & 511u);         // pz
            unsigned mask = (__ldg(&g_childbm[p >> 2]) >> ((p & 3u) * 8u)) & 0xFFu;
            float4 lo, hi;
            lo.x = (float)( mask       & 1u);
            lo.y = (float)((mask >> 1) & 1u);
            lo.z = (float)((mask >> 2) & 1u);
            lo.w = (float)((mask >> 3) & 1u);
            hi.x = (float)((mask >> 4) & 1u);
            hi.y = (float)((mask >> 5) & 1u);
            hi.z = (float)((mask >> 6) & 1u);
            hi.w = (float)((mask >> 7) & 1u);
            float4* occ4 = reinterpret_cast<float4*>(outOcc + 8 * (size_t)pos);
            occ4[0] = lo;
            occ4[1] = hi;
            pos++;
        }
    }
}

extern "C" void kernel_launch(void* const* d_in, const int* in_sizes, int n_in,
                              void* d_out, int out_size) {
    const float* leaf = (const float*)d_in[0];
    int n = in_sizes[0] / 3;
    float* out    = (float*)d_out;
    float* outPC  = out;                      // [n,3] parent coords (wrapped semantics)
    float* outOcc = out + (size_t)n * 3;      // [n,8] occupancy

    k_clear    <<<2048, 256>>>();
    k_scatter  <<<(n + 255) / 256, 256>>>(leaf, n);
    k_countscan<<<CBLK, TPB>>>();
    k_fill     <<<2048, 256>>>(outPC, outOcc, n);
    k_emit     <<<EBLK, TPB>>>(outPC, outOcc);
}

// round 13
// speedup vs baseline: 1.2209x; 1.1594x over previous
#include <cuda_runtime.h>
#include <cuda_bf16.h>
#include <cstdint>

// ---------------------------------------------------------------------------
// octree_level — replicating the reference AS EXECUTED (jax x64 disabled:
// int64 keys silently wrap to int32).
//
// Wrapped key <-> (x mod 256, y, z). Therefore:
//   parent class    c = (px mod 256, py, pz),  px = x>>1
//   negative classes (cmod >= 128) -> valid=False -> (-1,-1,-1) rows at FRONT
//   positive classes (cmod < 128)  -> coord rows sorted lex (cmod,py,pz)
//   occupancy(child) = exists leaf with (x mod 256, y, z) == child
//
// Pipeline: clear -> scatter(bitmaps) -> countscan -> emitA(compact class
// list, 4B/row) -> write(stream ALL output rows coalesced; sentinels inline).
// ---------------------------------------------------------------------------

#define NCW (1u << 23)   // child bitmap words (2^28 bits = 32 MB)
#define NPW (1u << 21)   // parent bitmap words (2^26 bits = 8 MB)
#define CBLK 512         // count blocks (cover all NPW words)
#define EBLK 256         // emit blocks (lower half only)
#define TPB  256
#define WPT  16          // words per thread: CBLK*TPB*WPT = 2^21 = NPW

__device__ unsigned int g_childbm[NCW];
__device__ unsigned int g_parbm[NPW];
__device__ unsigned int g_plist[1u << 21];   // class id per output row (valid range)
__device__ unsigned int g_bsum[CBLK];
__device__ unsigned int g_boff[EBLK];
__device__ unsigned int g_nneg;
__device__ unsigned int g_nend;
__device__ unsigned int g_ctr;   // blocks-done counter (reset by last block)

// ---- clear both bitmaps ----
__global__ void k_clear() {
    unsigned idx    = blockIdx.x * blockDim.x + threadIdx.x;
    unsigned stride = gridDim.x * blockDim.x;
    uint4 z = make_uint4(0u, 0u, 0u, 0u);
    uint4* c4 = reinterpret_cast<uint4*>(g_childbm);
    for (unsigned i = idx; i < NCW / 4; i += stride) c4[i] = z;
    uint4* p4 = reinterpret_cast<uint4*>(g_parbm);
    for (unsigned i = idx; i < NPW / 4; i += stride) p4[i] = z;
}

// ---- scatter leaves ----
__global__ void k_scatter(const float* __restrict__ leaf, int n) {
    int i = blockIdx.x * blockDim.x + threadIdx.x;
    if (i >= n) return;
    int x = (int)floorf(leaf[3 * i + 0]);
    int y = (int)floorf(leaf[3 * i + 1]);
    int z = (int)floorf(leaf[3 * i + 2]);
    unsigned pcls = (((unsigned)(x >> 1) & 255u) << 18)
                  | ((unsigned)(y >> 1) << 9) | (unsigned)(z >> 1);
    atomicOr(&g_parbm[pcls >> 5], 1u << (pcls & 31));
    unsigned pmp = ((((unsigned)x & 255u) >> 1) << 18)
                 | ((unsigned)(y >> 1) << 9) | (unsigned)(z >> 1);
    unsigned o = ((unsigned)(x & 1) << 2) | ((unsigned)(y & 1) << 1) | (unsigned)(z & 1);
    unsigned bit = (pmp << 3) | o;                 // < 2^28
    atomicOr(&g_childbm[bit >> 5], 1u << (bit & 31));
}

// ---- fused count + scan (last-block-does-scan, threadfence reduction) ----
__global__ void k_countscan() {
    __shared__ unsigned swarp[8];
    __shared__ bool s_last;
    int t = threadIdx.x;
    int lane = t & 31, warp = t >> 5;

    unsigned base = blockIdx.x * (TPB * WPT) + t * WPT;
    const uint4* w4 = reinterpret_cast<const uint4*>(g_parbm + base);
    unsigned c = 0;
#pragma unroll
    for (int v = 0; v < WPT / 4; v++) {
        uint4 a = w4[v];
        c += __popc(a.x) + __popc(a.y) + __popc(a.z) + __popc(a.w);
    }
    unsigned r = c;
#pragma unroll
    for (int off = 16; off; off >>= 1) r += __shfl_down_sync(0xffffffffu, r, off);
    if (lane == 0) swarp[warp] = r;
    __syncthreads();
    if (t == 0) {
        unsigned tot = 0;
#pragma unroll
        for (int i = 0; i < 8; i++) tot += swarp[i];
        g_bsum[blockIdx.x] = tot;
        __threadfence();
        unsigned d = atomicAdd(&g_ctr, 1u);
        s_last = (d == CBLK - 1);
    }
    __syncthreads();
    if (!s_last) return;

    __threadfence();
    unsigned vlo = g_bsum[t];
    unsigned vup = g_bsum[256 + t];
    unsigned ru = vup;
#pragma unroll
    for (int off = 16; off; off >>= 1) ru += __shfl_down_sync(0xffffffffu, ru, off);
    unsigned inc = vlo;
#pragma unroll
    for (int off = 1; off < 32; off <<= 1) {
        unsigned u = __shfl_up_sync(0xffffffffu, inc, off);
        if (lane >= off) inc += u;
    }
    __shared__ unsigned s_up[8], s_lo[8], s_base[8];
    if (lane == 0)  s_up[warp] = ru;
    if (lane == 31) s_lo[warp] = inc;
    __syncthreads();
    if (t == 0) {
        unsigned nneg = 0;
#pragma unroll
        for (int i = 0; i < 8; i++) nneg += s_up[i];
        unsigned acc = nneg;
#pragma unroll
        for (int i = 0; i < 8; i++) { s_base[i] = acc; acc += s_lo[i]; }
        g_nneg = nneg;
        g_nend = acc;
        g_ctr  = 0;            // reset for next graph replay (deterministic)
    }
    __syncthreads();
    g_boff[t] = s_base[warp] + inc - vlo;   // exclusive prefix + front offset
}

// ---- emitA: compact ordered class list (4B per valid row) ----
__global__ void k_emitA() {
    int t = threadIdx.x;
    int lane = t & 31, warp = t >> 5;
    unsigned base = blockIdx.x * (TPB * WPT) + t * WPT;   // words in lower half
    unsigned words[WPT];
    const uint4* w4 = reinterpret_cast<const uint4*>(g_parbm + base);
    unsigned c = 0;
#pragma unroll
    for (int v = 0; v < WPT / 4; v++) {
        uint4 a = w4[v];
        words[4 * v + 0] = a.x;
        words[4 * v + 1] = a.y;
        words[4 * v + 2] = a.z;
        words[4 * v + 3] = a.w;
        c += __popc(a.x) + __popc(a.y) + __popc(a.z) + __popc(a.w);
    }
    unsigned inc = c;
#pragma unroll
    for (int off = 1; off < 32; off <<= 1) {
        unsigned u = __shfl_up_sync(0xffffffffu, inc, off);
        if (lane >= off) inc += u;
    }
    __shared__ unsigned swsum[8], swbase[8];
    if (lane == 31) swsum[warp] = inc;
    __syncthreads();
    if (t == 0) {
        unsigned acc = 0;
#pragma unroll
        for (int i = 0; i < 8; i++) { swbase[i] = acc; acc += swsum[i]; }
    }
    __syncthreads();
    unsigned pos = g_boff[blockIdx.x] + swbase[warp] + (inc - c);

#pragma unroll
    for (int w = 0; w < WPT; w++) {
        unsigned word = words[w];
        unsigned wi = base + w;
        while (word) {
            int b = __ffs(word) - 1;
            word &= word - 1;
            g_plist[pos++] = wi * 32u + (unsigned)b;   // class id, < 2^25
        }
    }
}

// ---- write ALL output rows, fully coalesced ----
__global__ void k_write(float* __restrict__ outPC, float* __restrict__ outOcc, int n) {
    int r = blockIdx.x * blockDim.x + threadIdx.x;
    if (r >= n) return;
    unsigned nneg = g_nneg, nend = g_nend;
    bool valid = ((unsigned)r >= nneg) & ((unsigned)r < nend);

    float cx = -1.f, cy = -1.f, cz = -1.f;
    float4 lo = make_float4(0.f, 0.f, 0.f, 0.f);
    float4 hi = lo;
    if (valid) {
        unsigned p = g_plist[r];
        cx = (float)(p >> 18);
        cy = (float)((p >> 9) & 511u);
        cz = (float)(p & 511u);
        unsigned mask = (__ldg(&g_childbm[p >> 2]) >> ((p & 3u) * 8u)) & 0xFFu;
        lo.x = (float)( mask       & 1u);
        lo.y = (float)((mask >> 1) & 1u);
        lo.z = (float)((mask >> 2) & 1u);
        lo.w = (float)((mask >> 3) & 1u);
        hi.x = (float)((mask >> 4) & 1u);
        hi.y = (float)((mask >> 5) & 1u);
        hi.z = (float)((mask >> 6) & 1u);
        hi.w = (float)((mask >> 7) & 1u);
    }
    outPC[3 * r + 0] = cx;
    outPC[3 * r + 1] = cy;
    outPC[3 * r + 2] = cz;
    float4* occ4 = reinterpret_cast<float4*>(outOcc + 8 * (size_t)r);
    occ4[0] = lo;
    occ4[1] = hi;
}

extern "C" void kernel_launch(void* const* d_in, const int* in_sizes, int n_in,
                              void* d_out, int out_size) {
    const float* leaf = (const float*)d_in[0];
    int n = in_sizes[0] / 3;
    float* out    = (float*)d_out;
    float* outPC  = out;                      // [n,3] parent coords (wrapped semantics)
    float* outOcc = out + (size_t)n * 3;      // [n,8] occupancy

    k_clear    <<<2048, 256>>>();
    k_scatter  <<<(n + 255) / 256, 256>>>(leaf, n);
    k_countscan<<<CBLK, TPB>>>();
    k_emitA    <<<EBLK, TPB>>>();
    k_write    <<<(n + 255) / 256, 256>>>(outPC, outOcc, n);
}